// round 2
// baseline (speedup 1.0000x reference)
#include <cuda_runtime.h>
#include <cuda_fp16.h>
#include <math.h>

// ---------------------------------------------------------------------------
// Problem dims
// ---------------------------------------------------------------------------
#define SEQ   4096
#define IDIM  2048
#define HDIM  2048
#define GDIM  8192      // 4*HDIM
#define ODIM  2048

#define NBLK  148       // persistent scan blocks (== B300 SM count; GB300 has 152)
#define MAXROWS 56      // max 14 hidden units * 4 gates per block

// ---------------------------------------------------------------------------
// Device-global scratch (no allocations allowed)
// ---------------------------------------------------------------------------
__device__ float g_xg[(size_t)SEQ * GDIM];   // 134 MB precomputed input gates
__device__ float g_h[2][HDIM];               // double-buffered hidden state
__device__ int   g_bar;                      // global barrier counter

// ---------------------------------------------------------------------------
// f32x2 packed-FMA helpers (plain FFMA is half-rate on sm_103a)
// ---------------------------------------------------------------------------
__device__ __forceinline__ unsigned long long pack2(float x, float y) {
    unsigned long long r;
    asm("mov.b64 %0, {%1, %2};" : "=l"(r) : "f"(x), "f"(y));
    return r;
}
__device__ __forceinline__ void fma2(unsigned long long &d,
                                     unsigned long long a,
                                     unsigned long long b) {
    asm("fma.rn.f32x2 %0, %1, %2, %0;" : "+l"(d) : "l"(a), "l"(b));
}

// ---------------------------------------------------------------------------
// Kernel 0: reset the global barrier counter (graph-replay safe)
// ---------------------------------------------------------------------------
__global__ void zero_bar_kernel() { g_bar = 0; }

// ---------------------------------------------------------------------------
// Kernel 1: xg[s][r] = sum_k X[s][k] * Wih[r][k] + bih[r] + bhh[r]
// Tiled fp32 GEMM, BM=128 BN=64 BK=16, 256 threads, 8x4 micro-tile, f32x2 FMA.
// ---------------------------------------------------------------------------
#define BM 128
#define BN 64
#define BK 16
#define AS_STRIDE 136   // padded: conflict-free stores + 8B-aligned pair loads
#define BS_STRIDE 72

__global__ __launch_bounds__(256) void gemm_xg_kernel(
    const float* __restrict__ X, const float* __restrict__ Wih,
    const float* __restrict__ bih, const float* __restrict__ bhh)
{
    __shared__ float As[BK * AS_STRIDE];
    __shared__ float Bs[BK * BS_STRIDE];

    const int tid = threadIdx.x;
    const int bm = blockIdx.y * BM;
    const int bn = blockIdx.x * BN;
    const int m0 = (tid >> 4) * 8;   // 16 m-groups of 8
    const int n0 = (tid & 15) * 4;   // 16 n-groups of 4

    unsigned long long acc[4][4];
    const unsigned long long z = pack2(0.f, 0.f);
#pragma unroll
    for (int i = 0; i < 4; i++)
#pragma unroll
        for (int j = 0; j < 4; j++) acc[i][j] = z;

    for (int k0 = 0; k0 < IDIM; k0 += BK) {
        // Load A tile: 128 rows x 16 k  (512 float4, 2 per thread)
#pragma unroll
        for (int it = 0; it < 2; it++) {
            int idx = tid + it * 256;
            int row = idx >> 2, kc = idx & 3;
            float4 v = *(const float4*)(X + (size_t)(bm + row) * IDIM + k0 + kc * 4);
            As[(kc * 4 + 0) * AS_STRIDE + row] = v.x;
            As[(kc * 4 + 1) * AS_STRIDE + row] = v.y;
            As[(kc * 4 + 2) * AS_STRIDE + row] = v.z;
            As[(kc * 4 + 3) * AS_STRIDE + row] = v.w;
        }
        // Load B tile: 64 rows x 16 k  (256 float4, 1 per thread)
        {
            int row = tid >> 2, kc = tid & 3;
            float4 v = *(const float4*)(Wih + (size_t)(bn + row) * IDIM + k0 + kc * 4);
            Bs[(kc * 4 + 0) * BS_STRIDE + row] = v.x;
            Bs[(kc * 4 + 1) * BS_STRIDE + row] = v.y;
            Bs[(kc * 4 + 2) * BS_STRIDE + row] = v.z;
            Bs[(kc * 4 + 3) * BS_STRIDE + row] = v.w;
        }
        __syncthreads();

#pragma unroll
        for (int k = 0; k < BK; k++) {
            const unsigned long long* ap =
                (const unsigned long long*)(&As[k * AS_STRIDE + m0]);
            unsigned long long a2[4];
            a2[0] = ap[0]; a2[1] = ap[1]; a2[2] = ap[2]; a2[3] = ap[3];
            float4 bv = *(const float4*)(&Bs[k * BS_STRIDE + n0]);
            unsigned long long bd[4];
            bd[0] = pack2(bv.x, bv.x);
            bd[1] = pack2(bv.y, bv.y);
            bd[2] = pack2(bv.z, bv.z);
            bd[3] = pack2(bv.w, bv.w);
#pragma unroll
            for (int m2 = 0; m2 < 4; m2++)
#pragma unroll
                for (int n = 0; n < 4; n++) fma2(acc[m2][n], a2[m2], bd[n]);
        }
        __syncthreads();
    }

    // Epilogue: add bias, store
    float bias[4];
#pragma unroll
    for (int n = 0; n < 4; n++) {
        int col = bn + n0 + n;
        bias[n] = __ldg(bih + col) + __ldg(bhh + col);
    }
#pragma unroll
    for (int m2 = 0; m2 < 4; m2++) {
#pragma unroll
        for (int n = 0; n < 4; n++) {
            float2 f = *(float2*)&acc[m2][n];
            int row = bm + m0 + 2 * m2;
            int col = bn + n0 + n;
            g_xg[(size_t)row * GDIM + col]       = f.x + bias[n];
            g_xg[(size_t)(row + 1) * GDIM + col] = f.y + bias[n];
        }
    }
}

// ---------------------------------------------------------------------------
// Kernel 2: persistent LSTM scan.
// Block b owns hidden units [j0, j1): keeps the 4*(j1-j0) gate rows of W_hh as
// fp16 in shared memory for the whole scan (<= 224 KB). Per step:
//   - h read from L2 (__ldcg, double-buffered)
//   - 8 warps: warp = (k-half 0/1) x (row-group 0..3); lane covers 32 k
//   - warp shfl-reduce -> smem partials -> gate nonlinearities -> h write
//   - global barrier via atomic counter
// ---------------------------------------------------------------------------
__global__ __launch_bounds__(256) void scan_kernel(const float* __restrict__ Whh)
{
    extern __shared__ char smraw[];
    half*  w    = (half*)smraw;                                  // [rows][2048]
    float* part = (float*)(smraw + MAXROWS * HDIM * sizeof(half)); // [2][56]
    float* gf   = part + 2 * MAXROWS;                            // [56]
    float* cst  = gf + MAXROWS;                                  // [14]

    const int b   = blockIdx.x;
    const int tid = threadIdx.x;
    const int j0  = (b * HDIM) / NBLK;
    const int j1  = ((b + 1) * HDIM) / NBLK;
    const int nj  = j1 - j0;
    const int rows = 4 * nj;

    // ---- one-time: load this block's W_hh rows as fp16 into smem ----
    // smem row r = jl*4 + gate  <->  global row gate*HDIM + (j0 + jl)
    for (int idx = tid * 4; idx < rows * HDIM; idx += 256 * 4) {
        int r = idx >> 11;            // /2048
        int k = idx & (HDIM - 1);
        int jl = r >> 2, gate = r & 3;
        float4 v = *(const float4*)(Whh + (size_t)(gate * HDIM + j0 + jl) * HDIM + k);
        half* dst = w + (size_t)r * HDIM + k;
        dst[0] = __float2half_rn(v.x);
        dst[1] = __float2half_rn(v.y);
        dst[2] = __float2half_rn(v.z);
        dst[3] = __float2half_rn(v.w);
    }
    if (tid < nj) {
        cst[tid] = 0.f;
        g_h[0][j0 + tid] = 0.f;       // h0 = 0
    }
    __threadfence();
    __syncthreads();
    if (tid == 0) {
        atomicAdd(&g_bar, 1);
        while (*(volatile int*)&g_bar < NBLK) {}
    }
    __syncthreads();

    const int wid   = tid >> 5;
    const int lane  = tid & 31;
    const int khalf = wid >> 2;       // 0 / 1 : which 1024-wide k-half
    const int rg    = wid & 3;        // row group
    const int kbase = khalf * 1024;
    const int r0    = rg * 14;

    for (int s = 0; s < SEQ; s++) {
        const float* hb = g_h[s & 1];
        // load this lane's 32 h values (4 chunks of 8), L2-coherent
        float4 hv[4][2];
#pragma unroll
        for (int i = 0; i < 4; i++) {
            const float4* p = (const float4*)(hb + kbase + i * 256 + lane * 8);
            hv[i][0] = __ldcg(p);
            hv[i][1] = __ldcg(p + 1);
        }
        const int r1 = min(r0 + 14, rows);
        for (int r = r0; r < r1; r++) {
            const half* wrow = w + (size_t)r * HDIM + kbase;
            float acc = 0.f;
#pragma unroll
            for (int i = 0; i < 4; i++) {
                uint4 wv = *(const uint4*)(wrow + i * 256 + lane * 8);
                float2 f;
                f = __half22float2(*reinterpret_cast<const half2*>(&wv.x));
                acc = fmaf(f.x, hv[i][0].x, acc);
                acc = fmaf(f.y, hv[i][0].y, acc);
                f = __half22float2(*reinterpret_cast<const half2*>(&wv.y));
                acc = fmaf(f.x, hv[i][0].z, acc);
                acc = fmaf(f.y, hv[i][0].w, acc);
                f = __half22float2(*reinterpret_cast<const half2*>(&wv.z));
                acc = fmaf(f.x, hv[i][1].x, acc);
                acc = fmaf(f.y, hv[i][1].y, acc);
                f = __half22float2(*reinterpret_cast<const half2*>(&wv.w));
                acc = fmaf(f.x, hv[i][1].z, acc);
                acc = fmaf(f.y, hv[i][1].w, acc);
            }
#pragma unroll
            for (int o = 16; o; o >>= 1) acc += __shfl_xor_sync(0xffffffffu, acc, o);
            if (lane == 0) part[khalf * MAXROWS + r] = acc;
        }
        __syncthreads();

        if (tid < rows) {
            int gate = tid & 3, jl = tid >> 2;
            float g = part[tid] + part[MAXROWS + tid]
                    + __ldcg(&g_xg[(size_t)s * GDIM + gate * HDIM + j0 + jl]);
            gf[tid] = g;
        }
        __syncthreads();

        if (tid < nj) {
            float gi = gf[tid * 4 + 0];
            float gfo = gf[tid * 4 + 1];
            float gg = gf[tid * 4 + 2];
            float go = gf[tid * 4 + 3];
            float i_ = 1.f / (1.f + expf(-gi));
            float f_ = 1.f / (1.f + expf(-gfo));
            float g_ = tanhf(gg);
            float o_ = 1.f / (1.f + expf(-go));
            float c = f_ * cst[tid] + i_ * g_;
            cst[tid] = c;
            g_h[(s + 1) & 1][j0 + tid] = o_ * tanhf(c);
        }
        __threadfence();
        __syncthreads();
        if (tid == 0) {
            atomicAdd(&g_bar, 1);
            const int target = NBLK * (s + 2);
            while (*(volatile int*)&g_bar < target) {}
        }
        __syncthreads();
    }
    // final h = h_4096 lives in g_h[0]  (4096 is even)
}

// ---------------------------------------------------------------------------
// Kernel 3: out = h_last @ Wfc^T + bfc   (one warp per output)
// ---------------------------------------------------------------------------
__global__ __launch_bounds__(128) void fc_kernel(
    const float* __restrict__ Wfc, const float* __restrict__ bfc,
    float* __restrict__ out)
{
    const int o    = blockIdx.x * 4 + (threadIdx.x >> 5);
    const int lane = threadIdx.x & 31;
    const float* wr = Wfc + (size_t)o * HDIM;
    float acc = 0.f;
#pragma unroll
    for (int i = 0; i < 16; i++) {
        float4 wv = __ldg((const float4*)(wr + i * 128 + lane * 4));
        float4 hv = *(const float4*)(&g_h[0][i * 128 + lane * 4]);
        acc = fmaf(wv.x, hv.x, acc);
        acc = fmaf(wv.y, hv.y, acc);
        acc = fmaf(wv.z, hv.z, acc);
        acc = fmaf(wv.w, hv.w, acc);
    }
#pragma unroll
    for (int s = 16; s; s >>= 1) acc += __shfl_xor_sync(0xffffffffu, acc, s);
    if (lane == 0) out[o] = acc + __ldg(bfc + o);
}

// ---------------------------------------------------------------------------
// Launch
// ---------------------------------------------------------------------------
extern "C" void kernel_launch(void* const* d_in, const int* in_sizes, int n_in,
                              void* d_out, int out_size)
{
    const float* X    = (const float*)d_in[0];  // input_seq [1,4096,2048]
    const float* Wih  = (const float*)d_in[1];  // [8192,2048]
    const float* Whh  = (const float*)d_in[2];  // [8192,2048]
    const float* bih  = (const float*)d_in[3];  // [8192]
    const float* bhh  = (const float*)d_in[4];  // [8192]
    const float* Wfc  = (const float*)d_in[5];  // [2048,2048]
    const float* bfc  = (const float*)d_in[6];  // [2048]
    float* out = (float*)d_out;

    const int scan_smem = MAXROWS * HDIM * (int)sizeof(half)
                        + (2 * MAXROWS + MAXROWS + 16) * (int)sizeof(float);
    cudaFuncSetAttribute(scan_kernel,
                         cudaFuncAttributeMaxDynamicSharedMemorySize, scan_smem);

    zero_bar_kernel<<<1, 1>>>();

    dim3 ggrid(GDIM / BN, SEQ / BM);   // (128, 32)
    gemm_xg_kernel<<<ggrid, 256>>>(X, Wih, bih, bhh);

    scan_kernel<<<NBLK, 256, scan_smem>>>(Whh);

    fc_kernel<<<ODIM / 4, 128>>>(Wfc, bfc, out);
}

// round 5
// speedup vs baseline: 1.2074x; 1.2074x over previous
#include <cuda_runtime.h>
#include <cuda_fp16.h>
#include <math.h>

// ---------------------------------------------------------------------------
// Problem dims
// ---------------------------------------------------------------------------
#define SEQ   4096
#define IDIM  2048
#define HDIM  2048
#define GDIM  8192      // 4*HDIM
#define ODIM  2048

#define NBLK  148       // persistent scan blocks (1 per SM)
#define MAXROWS 56      // max 14 hidden units * 4 gates per block
#define FLAGSTRIDE 32   // one flag per 128B line (spread across LTS slices)

// ---------------------------------------------------------------------------
// Device-global scratch (no allocations allowed)
// ---------------------------------------------------------------------------
__device__ float g_xg[(size_t)SEQ * GDIM];   // 134 MB precomputed input gates
__device__ float g_h[2][HDIM];               // double-buffered hidden state
__device__ int   g_flag[NBLK * FLAGSTRIDE];  // distributed barrier flags

// ---------------------------------------------------------------------------
// Fast gate math (tanh.approx, sm_75+)
// ---------------------------------------------------------------------------
__device__ __forceinline__ float tanh_fast(float x) {
    float y; asm("tanh.approx.f32 %0, %1;" : "=f"(y) : "f"(x)); return y;
}
__device__ __forceinline__ float sigmoid_fast(float x) {
    return 0.5f + 0.5f * tanh_fast(0.5f * x);
}
__device__ __forceinline__ unsigned int f2tf32(float f) {
    unsigned int u; asm("cvt.rna.tf32.f32 %0, %1;" : "=r"(u) : "f"(f)); return u;
}

// ---------------------------------------------------------------------------
// Kernel 0: reset barrier flags (graph-replay safe)
// ---------------------------------------------------------------------------
__global__ void zero_flags_kernel() {
    if (threadIdx.x < NBLK) g_flag[threadIdx.x * FLAGSTRIDE] = 0;
}

// ---------------------------------------------------------------------------
// Kernel 1: xg = X @ Wih^T + bih + bhh  via tf32 mma.sync.m16n8k8
// Block 128x128, 8 warps (2x4), warp tile 64x32, BK=32.
// ---------------------------------------------------------------------------
#define GBM 128
#define GBN 128
#define GBK 32
#define GSTR 36   // padded smem stride (floats)

__global__ __launch_bounds__(256) void gemm_xg_mma(
    const float* __restrict__ X, const float* __restrict__ Wih,
    const float* __restrict__ bih, const float* __restrict__ bhh)
{
    __shared__ float As[GBM * GSTR];
    __shared__ float Bs[GBN * GSTR];

    const int tid  = threadIdx.x;
    const int warp = tid >> 5;
    const int lane = tid & 31;
    const int wm   = warp >> 2;          // 0..1 -> m offset *64
    const int wn   = warp & 3;           // 0..3 -> n offset *32
    const int bm   = blockIdx.y * GBM;   // seq rows
    const int bn   = blockIdx.x * GBN;   // gate rows

    float c[4][4][4];
#pragma unroll
    for (int mt = 0; mt < 4; mt++)
#pragma unroll
        for (int nt = 0; nt < 4; nt++)
#pragma unroll
            for (int i = 0; i < 4; i++) c[mt][nt][i] = 0.f;

    const int lrow = tid >> 3;           // 0..31
    const int lc4  = (tid & 7) * 4;      // 0..28

    for (int k0 = 0; k0 < IDIM; k0 += GBK) {
#pragma unroll
        for (int it = 0; it < 4; it++) {
            int row = lrow + it * 32;
            float4 va = *(const float4*)(X + (size_t)(bm + row) * IDIM + k0 + lc4);
            float* da = &As[row * GSTR + lc4];
            da[0] = __uint_as_float(f2tf32(va.x));
            da[1] = __uint_as_float(f2tf32(va.y));
            da[2] = __uint_as_float(f2tf32(va.z));
            da[3] = __uint_as_float(f2tf32(va.w));
            float4 vb = *(const float4*)(Wih + (size_t)(bn + row) * IDIM + k0 + lc4);
            float* db = &Bs[row * GSTR + lc4];
            db[0] = __uint_as_float(f2tf32(vb.x));
            db[1] = __uint_as_float(f2tf32(vb.y));
            db[2] = __uint_as_float(f2tf32(vb.z));
            db[3] = __uint_as_float(f2tf32(vb.w));
        }
        __syncthreads();

#pragma unroll
        for (int ks = 0; ks < 4; ks++) {
            const int kk = ks * 8 + (lane & 3);
            unsigned int a[4][4], b[4][2];
#pragma unroll
            for (int mt = 0; mt < 4; mt++) {
                int mrow = wm * 64 + mt * 16 + (lane >> 2);
                a[mt][0] = __float_as_uint(As[mrow * GSTR + kk]);
                a[mt][1] = __float_as_uint(As[(mrow + 8) * GSTR + kk]);
                a[mt][2] = __float_as_uint(As[mrow * GSTR + kk + 4]);
                a[mt][3] = __float_as_uint(As[(mrow + 8) * GSTR + kk + 4]);
            }
#pragma unroll
            for (int nt = 0; nt < 4; nt++) {
                int ncol = wn * 32 + nt * 8 + (lane >> 2);
                b[nt][0] = __float_as_uint(Bs[ncol * GSTR + kk]);
                b[nt][1] = __float_as_uint(Bs[ncol * GSTR + kk + 4]);
            }
#pragma unroll
            for (int mt = 0; mt < 4; mt++)
#pragma unroll
                for (int nt = 0; nt < 4; nt++) {
                    asm volatile(
                        "mma.sync.aligned.m16n8k8.row.col.f32.tf32.tf32.f32 "
                        "{%0,%1,%2,%3}, {%4,%5,%6,%7}, {%8,%9}, {%0,%1,%2,%3};"
                        : "+f"(c[mt][nt][0]), "+f"(c[mt][nt][1]),
                          "+f"(c[mt][nt][2]), "+f"(c[mt][nt][3])
                        : "r"(a[mt][0]), "r"(a[mt][1]), "r"(a[mt][2]), "r"(a[mt][3]),
                          "r"(b[nt][0]), "r"(b[nt][1]));
                }
        }
        __syncthreads();
    }

    // Epilogue
#pragma unroll
    for (int nt = 0; nt < 4; nt++) {
        int ncol = bn + wn * 32 + nt * 8 + (lane & 3) * 2;
        float b0 = __ldg(bih + ncol) + __ldg(bhh + ncol);
        float b1 = __ldg(bih + ncol + 1) + __ldg(bhh + ncol + 1);
#pragma unroll
        for (int mt = 0; mt < 4; mt++) {
            int mrow = bm + wm * 64 + mt * 16 + (lane >> 2);
            float* p0 = &g_xg[(size_t)mrow * GDIM + ncol];
            float* p1 = &g_xg[(size_t)(mrow + 8) * GDIM + ncol];
            p0[0] = c[mt][nt][0] + b0;
            p0[1] = c[mt][nt][1] + b1;
            p1[0] = c[mt][nt][2] + b0;
            p1[1] = c[mt][nt][3] + b1;
        }
    }
}

// ---------------------------------------------------------------------------
// Kernel 2: persistent LSTM scan, fp16 weights in smem, HFMA2 inner loop,
// distributed flag barrier.
// ---------------------------------------------------------------------------
__global__ __launch_bounds__(256) void scan_kernel(const float* __restrict__ Whh)
{
    extern __shared__ char smraw[];
    half*  w    = (half*)smraw;                                    // [rows][2048]
    float* part = (float*)(smraw + (size_t)MAXROWS * HDIM * sizeof(half)); // [2][56]
    float* gf   = part + 2 * MAXROWS;                              // [56]
    float* cst  = gf + MAXROWS;                                    // [14]

    const int b   = blockIdx.x;
    const int tid = threadIdx.x;
    const int j0  = (b * HDIM) / NBLK;
    const int j1  = ((b + 1) * HDIM) / NBLK;
    const int nj  = j1 - j0;
    const int rows = 4 * nj;

    // ---- one-time: load this block's W_hh rows as fp16 into smem ----
    for (int idx = tid * 4; idx < rows * HDIM; idx += 256 * 4) {
        int r = idx >> 11;
        int k = idx & (HDIM - 1);
        int jl = r >> 2, gate = r & 3;
        float4 v = *(const float4*)(Whh + (size_t)(gate * HDIM + j0 + jl) * HDIM + k);
        half* dst = w + (size_t)r * HDIM + k;
        dst[0] = __float2half_rn(v.x);
        dst[1] = __float2half_rn(v.y);
        dst[2] = __float2half_rn(v.z);
        dst[3] = __float2half_rn(v.w);
    }
    if (tid < nj) {
        cst[tid] = 0.f;
        g_h[0][j0 + tid] = 0.f;
    }
    // initial barrier: target 1
    __threadfence();
    __syncthreads();
    if (tid == 0) g_flag[b * FLAGSTRIDE] = 1;
    if (tid < NBLK) {
        while (*(volatile int*)&g_flag[tid * FLAGSTRIDE] < 1) {}
    }
    __syncthreads();

    const int wid   = tid >> 5;
    const int lane  = tid & 31;
    const int khalf = wid >> 2;       // which 1024-wide k-half
    const int rg    = wid & 3;        // row group
    const int kbase = khalf * 1024;
    const int r0    = rg * 14;
    const int gate_t = tid & 3, jl_t = tid >> 2;

    const half2 hz = __floats2half2_rn(0.f, 0.f);

    for (int s = 0; s < SEQ; s++) {
        const float* hb = g_h[s & 1];

        // prefetch xg for this step (consumed after the matvec)
        float xval = 0.f;
        if (tid < rows)
            xval = __ldcg(&g_xg[(size_t)s * GDIM + gate_t * HDIM + j0 + jl_t]);

        // load h (L2) and convert to half2
        half2 hh[16];
#pragma unroll
        for (int i = 0; i < 4; i++) {
            const float4* p = (const float4*)(hb + kbase + i * 256 + lane * 8);
            float4 v0 = __ldcg(p);
            float4 v1 = __ldcg(p + 1);
            hh[i * 4 + 0] = __floats2half2_rn(v0.x, v0.y);
            hh[i * 4 + 1] = __floats2half2_rn(v0.z, v0.w);
            hh[i * 4 + 2] = __floats2half2_rn(v1.x, v1.y);
            hh[i * 4 + 3] = __floats2half2_rn(v1.z, v1.w);
        }

        const int r1 = min(r0 + 14, rows);
        for (int r = r0; r < r1; r++) {
            const uint4* wp = (const uint4*)(w + (size_t)r * HDIM + kbase);
            half2 a0 = hz, a1 = hz;
#pragma unroll
            for (int i = 0; i < 4; i++) {
                uint4 wv = wp[i * 32 + lane];
                a0 = __hfma2(*(const half2*)&wv.x, hh[i * 4 + 0], a0);
                a1 = __hfma2(*(const half2*)&wv.y, hh[i * 4 + 1], a1);
                a0 = __hfma2(*(const half2*)&wv.z, hh[i * 4 + 2], a0);
                a1 = __hfma2(*(const half2*)&wv.w, hh[i * 4 + 3], a1);
            }
            float2 f0 = __half22float2(a0);
            float2 f1 = __half22float2(a1);
            float acc = (f0.x + f0.y) + (f1.x + f1.y);
#pragma unroll
            for (int o = 16; o; o >>= 1) acc += __shfl_xor_sync(0xffffffffu, acc, o);
            if (lane == 0) part[khalf * MAXROWS + r] = acc;
        }
        __syncthreads();

        if (tid < rows) {
            float g = part[tid] + part[MAXROWS + tid] + xval;
            gf[tid] = (gate_t == 2) ? tanh_fast(g) : sigmoid_fast(g);
        }
        __syncthreads();

        if (tid < nj) {
            float i_ = gf[tid * 4 + 0];
            float f_ = gf[tid * 4 + 1];
            float g_ = gf[tid * 4 + 2];
            float o_ = gf[tid * 4 + 3];
            float c = f_ * cst[tid] + i_ * g_;
            cst[tid] = c;
            g_h[(s + 1) & 1][j0 + tid] = o_ * tanh_fast(c);
        }

        // distributed barrier
        __threadfence();
        __syncthreads();
        if (tid == 0) g_flag[b * FLAGSTRIDE] = s + 2;
        if (tid < NBLK) {
            const int target = s + 2;
            while (*(volatile int*)&g_flag[tid * FLAGSTRIDE] < target) {}
        }
        __syncthreads();
    }
    // final h in g_h[0] (SEQ even)
}

// ---------------------------------------------------------------------------
// Kernel 3: out = h_last @ Wfc^T + bfc
// ---------------------------------------------------------------------------
__global__ __launch_bounds__(128) void fc_kernel(
    const float* __restrict__ Wfc, const float* __restrict__ bfc,
    float* __restrict__ out)
{
    const int o    = blockIdx.x * 4 + (threadIdx.x >> 5);
    const int lane = threadIdx.x & 31;
    const float* wr = Wfc + (size_t)o * HDIM;
    float acc = 0.f;
#pragma unroll
    for (int i = 0; i < 16; i++) {
        float4 wv = __ldg((const float4*)(wr + i * 128 + lane * 4));
        float4 hv = *(const float4*)(&g_h[0][i * 128 + lane * 4]);
        acc = fmaf(wv.x, hv.x, acc);
        acc = fmaf(wv.y, hv.y, acc);
        acc = fmaf(wv.z, hv.z, acc);
        acc = fmaf(wv.w, hv.w, acc);
    }
#pragma unroll
    for (int s = 16; s; s >>= 1) acc += __shfl_xor_sync(0xffffffffu, acc, s);
    if (lane == 0) out[o] = acc + __ldg(bfc + o);
}

// ---------------------------------------------------------------------------
// Launch
// ---------------------------------------------------------------------------
extern "C" void kernel_launch(void* const* d_in, const int* in_sizes, int n_in,
                              void* d_out, int out_size)
{
    const float* X    = (const float*)d_in[0];
    const float* Wih  = (const float*)d_in[1];
    const float* Whh  = (const float*)d_in[2];
    const float* bih  = (const float*)d_in[3];
    const float* bhh  = (const float*)d_in[4];
    const float* Wfc  = (const float*)d_in[5];
    const float* bfc  = (const float*)d_in[6];
    float* out = (float*)d_out;

    const int scan_smem = MAXROWS * HDIM * (int)sizeof(half)
                        + (2 * MAXROWS + MAXROWS + 16) * (int)sizeof(float);
    cudaFuncSetAttribute(scan_kernel,
                         cudaFuncAttributeMaxDynamicSharedMemorySize, scan_smem);

    zero_flags_kernel<<<1, 256>>>();

    dim3 ggrid(GDIM / GBN, SEQ / GBM);   // (64, 32)
    gemm_xg_mma<<<ggrid, 256>>>(X, Wih, bih, bhh);

    scan_kernel<<<NBLK, 256, scan_smem>>>(Whh);

    fc_kernel<<<ODIM / 4, 128>>>(Wfc, bfc, out);
}